// round 14
// baseline (speedup 1.0000x reference)
#include <cuda_runtime.h>
#include <cuda_fp16.h>
#include <cstdint>
#include <cstddef>

#define V_N 50000
#define E_N 160000
#define SA  136      // bf16 row stride for weight/A images (272 B) — conflict-free
#define SG  132      // f32 row stride for G staging (528 B) — conflict-free (4g mod 32)

typedef unsigned long long ull;
typedef unsigned int u32;

// ---------------------------------------------------------------------------
// Device scratch
// g_tab: per (pass p, side s): [V][128] fp16, slab by = 2p+s.
// g_G:   per pass, segment-summed relu'd hidden (f32).
// g_wimg: 24 weight images (16 W1 + 8 W2), each [128 n][SA k] bf16 hi+lo.
// ---------------------------------------------------------------------------
__device__ __align__(128) __half g_tab[(size_t)16 * V_N * 128];
__device__ __align__(128) float  g_G[(size_t)8 * V_N * 128];
__device__ __align__(256) unsigned short g_wimg[(size_t)24 * 2 * 128 * SA];

#define WIMG_BLK   (2 * 128 * SA)
#define WIMG_BYTES (WIMG_BLK * 2)     // 69632 B

// pre_mma smem (A hi/lo pre-split + double-buffered B): 208896 B
#define SM_A_HI  0
#define SM_A_LO  34816
#define SM_B0    69632
#define SM_B1    139264
#define SM_PRE   208896

// out_mma smem (double-buffered raw f32 G staging + single B image): 204800 B
#define G_STAGE  (128 * SG * 4)       // 67584 B
#define SM_G0    0
#define SM_G1    67584
#define SM_OB    135168
#define SM_OUT   204800

// ---------------------------------------------------------------------------
static __device__ __forceinline__ u32 smem_u32(const void* p) {
    u32 a;
    asm("{ .reg .u64 t; cvta.to.shared.u64 t, %1; cvt.u32.u64 %0, t; }"
        : "=r"(a) : "l"(p));
    return a;
}
#define CP_ASYNC16(dst_u32, src_ptr) \
    asm volatile("cp.async.ca.shared.global [%0], [%1], 16;" \
                 :: "r"(dst_u32), "l"(src_ptr) : "memory")
#define CP_COMMIT()  asm volatile("cp.async.commit_group;" ::: "memory")
#define CP_WAIT(n)   asm volatile("cp.async.wait_group %0;" :: "n"(n) : "memory")

static __device__ __forceinline__ void mma16816(float d[4], const u32 a[4], const u32 b[2]) {
    asm volatile(
        "mma.sync.aligned.m16n8k16.row.col.f32.bf16.bf16.f32 "
        "{%0,%1,%2,%3}, {%4,%5,%6,%7}, {%8,%9}, {%0,%1,%2,%3};"
        : "+f"(d[0]), "+f"(d[1]), "+f"(d[2]), "+f"(d[3])
        : "r"(a[0]), "r"(a[1]), "r"(a[2]), "r"(a[3]), "r"(b[0]), "r"(b[1]));
}

// Split a float2 into packed bf16x2 hi (truncated) and lo (residual, rn).
static __device__ __forceinline__ void split2(float2 v, u32& hi, u32& lo) {
    u32 ux = __float_as_uint(v.x), uy = __float_as_uint(v.y);
    hi = __byte_perm(ux, uy, 0x7632);
    float rx = v.x - __uint_as_float(ux & 0xFFFF0000u);
    float ry = v.y - __uint_as_float(uy & 0xFFFF0000u);
    asm("cvt.rn.bf16x2.f32 %0, %1, %2;" : "=r"(lo) : "f"(ry), "f"(rx));
}

// ---------------------------------------------------------------------------
// Split an f32 [128 rows][128 k] tile into bf16 hi/lo smem tiles (stride SA).
// pre_mma only (A resident across 16 iterations). 512 threads:
// thread t -> row t>>2, 32-float quarter (t&3).
// ---------------------------------------------------------------------------
static __device__ __forceinline__ void load_A_tile(const float* __restrict__ base,
                                                   int v0, char* sm, int t) {
    const int row = t >> 2;
    const int q0  = (t & 3) * 32;
    int vg = v0 + row; if (vg >= V_N) vg = V_N - 1;
    const float4* src = reinterpret_cast<const float4*>(base + (size_t)vg * 128 + q0);
    char* hi = sm + SM_A_HI + (size_t)(row * SA + q0) * 2;
    char* lo = sm + SM_A_LO + (size_t)(row * SA + q0) * 2;
#pragma unroll
    for (int q = 0; q < 8; ++q) {
        float4 x = src[q];
        u32 h01, l01, h23, l23;
        split2(make_float2(x.x, x.y), h01, l01);
        split2(make_float2(x.z, x.w), h23, l23);
        *reinterpret_cast<ull*>(hi + q * 8) = ((ull)h23 << 32) | h01;
        *reinterpret_cast<ull*>(lo + q * 8) = ((ull)l23 << 32) | l01;
    }
}

// ---------------------------------------------------------------------------
// 3-split MMA, 16 warps, warp tile 32m x 32n: m0=(w>>2)*32, n0=(w&3)*32.
// Pre-split smem A path (pre_mma). d[8][4].
// ---------------------------------------------------------------------------
static __device__ __forceinline__ void mma_block(const char* sm, const char* Bbuf,
                                                 int w, int lane, float d[8][4]) {
    const int g  = lane >> 2;
    const int tg = lane & 3;
    const int m0 = (w >> 2) * 32;
    const int n0 = (w & 3) * 32;
    const char* Ah = sm + SM_A_HI;
    const char* Al = sm + SM_A_LO;
    const char* Bh = Bbuf;
    const char* Bl = Bbuf + 34816;

#pragma unroll
    for (int ks = 0; ks < 8; ++ks) {
        const int kb = ks * 16;
        u32 ah[2][4], al[2][4], bh[4][2], bl[4][2];
#pragma unroll
        for (int i = 0; i < 2; ++i) {
            int m = m0 + i * 16 + g;
            size_t o0 = (size_t)(m * SA + kb + 2 * tg) * 2;
            size_t o1 = (size_t)((m + 8) * SA + kb + 2 * tg) * 2;
            ah[i][0] = *reinterpret_cast<const u32*>(Ah + o0);
            ah[i][1] = *reinterpret_cast<const u32*>(Ah + o1);
            ah[i][2] = *reinterpret_cast<const u32*>(Ah + o0 + 16);
            ah[i][3] = *reinterpret_cast<const u32*>(Ah + o1 + 16);
            al[i][0] = *reinterpret_cast<const u32*>(Al + o0);
            al[i][1] = *reinterpret_cast<const u32*>(Al + o1);
            al[i][2] = *reinterpret_cast<const u32*>(Al + o0 + 16);
            al[i][3] = *reinterpret_cast<const u32*>(Al + o1 + 16);
        }
#pragma unroll
        for (int j = 0; j < 4; ++j) {
            int n = n0 + j * 8 + g;
            size_t o = (size_t)(n * SA + kb + 2 * tg) * 2;
            bh[j][0] = *reinterpret_cast<const u32*>(Bh + o);
            bh[j][1] = *reinterpret_cast<const u32*>(Bh + o + 16);
            bl[j][0] = *reinterpret_cast<const u32*>(Bl + o);
            bl[j][1] = *reinterpret_cast<const u32*>(Bl + o + 16);
        }
#pragma unroll
        for (int i = 0; i < 2; ++i)
#pragma unroll
            for (int j = 0; j < 4; ++j) {
                mma16816(d[i * 4 + j], ah[i], bh[j]);
                mma16816(d[i * 4 + j], ah[i], bl[j]);
                mma16816(d[i * 4 + j], al[i], bh[j]);
            }
    }
}

// ---------------------------------------------------------------------------
// 3-split MMA from RAW f32 G staging (out_mma): per-fragment register split.
// Gs: f32 [128 rows][SG]. Bbuf: pre-split bf16 image (stride SA). d[8][4].
// ---------------------------------------------------------------------------
static __device__ __forceinline__ void mma_block_reg(const float* Gs, const char* Bbuf,
                                                     int w, int lane, float d[8][4]) {
    const int g  = lane >> 2;
    const int tg = lane & 3;
    const int m0 = (w >> 2) * 32;
    const int n0 = (w & 3) * 32;
    const char* Bh = Bbuf;
    const char* Bl = Bbuf + 34816;

#pragma unroll
    for (int ks = 0; ks < 8; ++ks) {
        const int kb = ks * 16;
        u32 ah[2][4], al[2][4], bh[4][2], bl[4][2];
#pragma unroll
        for (int i = 0; i < 2; ++i) {
            int m = m0 + i * 16 + g;
            const float* r0 = Gs + m * SG + kb + 2 * tg;
            const float* r1 = Gs + (m + 8) * SG + kb + 2 * tg;
            split2(*reinterpret_cast<const float2*>(r0),     ah[i][0], al[i][0]);
            split2(*reinterpret_cast<const float2*>(r1),     ah[i][1], al[i][1]);
            split2(*reinterpret_cast<const float2*>(r0 + 8), ah[i][2], al[i][2]);
            split2(*reinterpret_cast<const float2*>(r1 + 8), ah[i][3], al[i][3]);
        }
#pragma unroll
        for (int j = 0; j < 4; ++j) {
            int n = n0 + j * 8 + g;
            size_t o = (size_t)(n * SA + kb + 2 * tg) * 2;
            bh[j][0] = *reinterpret_cast<const u32*>(Bh + o);
            bh[j][1] = *reinterpret_cast<const u32*>(Bh + o + 16);
            bl[j][0] = *reinterpret_cast<const u32*>(Bl + o);
            bl[j][1] = *reinterpret_cast<const u32*>(Bl + o + 16);
        }
#pragma unroll
        for (int i = 0; i < 2; ++i)
#pragma unroll
            for (int j = 0; j < 4; ++j) {
                mma16816(d[i * 4 + j], ah[i], bh[j]);
                mma16816(d[i * 4 + j], ah[i], bl[j]);
                mma16816(d[i * 4 + j], al[i], bh[j]);
            }
    }
}

// Prefetch one weight image (69632 B = 4352 x 16B) with 512 threads + commit.
static __device__ __forceinline__ void prefetch_W(u32 dst_sb, const char* src, int t) {
#pragma unroll
    for (int i = 0; i < 9; ++i) {
        int idx = i * 512 + t;
        if (idx < 4352)
            CP_ASYNC16(dst_sb + (u32)(idx * 16), src + idx * 16);
    }
    CP_COMMIT();
}

// Prefetch one raw f32 G tile into staging (row stride SG*4=528 B) + commit.
// 512 threads: thread t -> row t>>2, 128B quarter (t&3).
static __device__ __forceinline__ void prefetch_G(u32 dst_sb, const float* slab,
                                                  int v0, int t) {
    const int row = t >> 2;
    int vg = v0 + row; if (vg >= V_N) vg = V_N - 1;
    const char* src = reinterpret_cast<const char*>(slab + (size_t)vg * 128) + (t & 3) * 128;
    u32 dst = dst_sb + (u32)(row * (SG * 4) + (t & 3) * 128);
#pragma unroll
    for (int c = 0; c < 8; ++c)
        CP_ASYNC16(dst + c * 16, src + c * 16);
    CP_COMMIT();
}

// ---------------------------------------------------------------------------
// Kernel: build weight images (blocks 0..23) + zero g_G (blocks 24..).
// ---------------------------------------------------------------------------
#define ZERO_BLOCKS 2000
__global__ void w_prep_kernel(const float* __restrict__ W1, const float* __restrict__ W2) {
    const int blk = blockIdx.x;
    if (blk < 24) {
        const float* src = (blk < 16) ? (W1 + (size_t)blk * 16384)
                                      : (W2 + (size_t)(blk - 16) * 16384);
        unsigned short* hi = g_wimg + (size_t)blk * WIMG_BLK;
        unsigned short* lo = hi + 128 * SA;
        for (int idx = threadIdx.x; idx < 16384; idx += blockDim.x) {
            int n = idx >> 7, k = idx & 127;
            float x = src[(size_t)k * 128 + n];
            u32 u = __float_as_uint(x);
            float r = x - __uint_as_float(u & 0xFFFF0000u);
            u32 lob;
            asm("cvt.rn.bf16x2.f32 %0, %1, %2;" : "=r"(lob) : "f"(0.0f), "f"(r));
            hi[n * SA + k] = (unsigned short)(u >> 16);
            lo[n * SA + k] = (unsigned short)(lob & 0xFFFF);
        }
    } else {
        const int i = (blk - 24) * 256 + threadIdx.x;
        float4* g4 = reinterpret_cast<float4*>(g_G);
#pragma unroll
        for (int c = 0; c < 25; ++c)
            g4[(size_t)i + (size_t)c * (ZERO_BLOCKS * 256)] = make_float4(0.f, 0.f, 0.f, 0.f);
    }
}

// ---------------------------------------------------------------------------
// Kernel: tab[by] = emb @ W1blk[by] for all 16 by (fp16 out). 512 threads.
// ---------------------------------------------------------------------------
__global__ __launch_bounds__(512, 1)
void pre_mma(const float* __restrict__ emb) {
    extern __shared__ char sm[];
    u32 sb = smem_u32(sm);
    const int t = threadIdx.x, w = t >> 5, lane = t & 31;
    const int v0 = blockIdx.x * 128;
    const int g = lane >> 2, tg = lane & 3;
    const int m0 = (w >> 2) * 32, n0 = (w & 3) * 32;
    const char* wbase = reinterpret_cast<const char*>(g_wimg);

    prefetch_W(sb + SM_B0, wbase, t);
    load_A_tile(emb, v0, sm, t);

    for (int by = 0; by < 16; ++by) {
        const u32 cur = (by & 1) ? SM_B1 : SM_B0;
        const u32 nxt = (by & 1) ? SM_B0 : SM_B1;
        if (by + 1 < 16) {
            prefetch_W(sb + nxt, wbase + (size_t)(by + 1) * WIMG_BYTES, t);
            CP_WAIT(1);
        } else {
            CP_WAIT(0);
        }
        __syncthreads();

        float d[8][4];
#pragma unroll
        for (int i = 0; i < 8; ++i) { d[i][0] = d[i][1] = d[i][2] = d[i][3] = 0.f; }

        mma_block(sm, sm + cur, w, lane, d);

        __half* base = g_tab + (size_t)by * V_N * 128;
#pragma unroll
        for (int i = 0; i < 2; ++i) {
            int vA = v0 + m0 + i * 16 + g;
            int vB = vA + 8;
#pragma unroll
            for (int j = 0; j < 4; ++j) {
                int col = n0 + j * 8 + 2 * tg;
                if (vA < V_N)
                    *reinterpret_cast<__half2*>(base + (size_t)vA * 128 + col) =
                        __floats2half2_rn(d[i * 4 + j][0], d[i * 4 + j][1]);
                if (vB < V_N)
                    *reinterpret_cast<__half2*>(base + (size_t)vB * 128 + col) =
                        __floats2half2_rn(d[i * 4 + j][2], d[i * 4 + j][3]);
            }
        }
        __syncthreads();   // all warps done with cur before it becomes prefetch dst
    }
}

// ---------------------------------------------------------------------------
// Kernel: edge phase — fp16 gather + add + relu + f32 vector-atomic scatter.
// ---------------------------------------------------------------------------
__global__ __launch_bounds__(256)
void edge_kernel(const int* __restrict__ a0p, const int* __restrict__ a1p,
                 const int* __restrict__ a2p, const int* __restrict__ a3p) {
    const int t    = threadIdx.x;
    const int p    = blockIdx.y;
    const int l    = p >> 1, ep = p & 1;
    const int* adj = (l == 0) ? a0p : (l == 1) ? a1p : (l == 2) ? a2p : a3p;

    const int e    = blockIdx.x * 16 + (t >> 4);
    const int half = t & 15;

    int2 sd = reinterpret_cast<const int2*>(adj)[e];
    int tgt = ep ? sd.y : sd.x;

    const __half* A = g_tab + (size_t)(2 * p) * V_N * 128;
    const __half* B = A + (size_t)V_N * 128;

    uint4 av = *reinterpret_cast<const uint4*>(A + (size_t)sd.x * 128 + half * 8);
    uint4 bv = *reinterpret_cast<const uint4*>(B + (size_t)sd.y * 128 + half * 8);

    float2 a0 = __half22float2(*reinterpret_cast<__half2*>(&av.x));
    float2 a1 = __half22float2(*reinterpret_cast<__half2*>(&av.y));
    float2 a2 = __half22float2(*reinterpret_cast<__half2*>(&av.z));
    float2 a3 = __half22float2(*reinterpret_cast<__half2*>(&av.w));
    float2 b0 = __half22float2(*reinterpret_cast<__half2*>(&bv.x));
    float2 b1 = __half22float2(*reinterpret_cast<__half2*>(&bv.y));
    float2 b2 = __half22float2(*reinterpret_cast<__half2*>(&bv.z));
    float2 b3 = __half22float2(*reinterpret_cast<__half2*>(&bv.w));

    float4 h0 = make_float4(fmaxf(a0.x + b0.x, 0.f), fmaxf(a0.y + b0.y, 0.f),
                            fmaxf(a1.x + b1.x, 0.f), fmaxf(a1.y + b1.y, 0.f));
    float4 h1 = make_float4(fmaxf(a2.x + b2.x, 0.f), fmaxf(a2.y + b2.y, 0.f),
                            fmaxf(a3.x + b3.x, 0.f), fmaxf(a3.y + b3.y, 0.f));

    float* gq = g_G + ((size_t)p * V_N + tgt) * 128 + half * 8;
    atomicAdd(reinterpret_cast<float4*>(gq), h0);
    atomicAdd(reinterpret_cast<float4*>(gq + 4), h1);
}

// ---------------------------------------------------------------------------
// Kernel: out = relu( sum_p G_p @ W2_p ), K=1024 in registers. 512 threads.
// G streamed through double-buffered raw-f32 staging; per-fragment reg split.
// Pipeline commit order per iter p: [G(p+1)] before mma, [B(p+1)] after.
// At iter p+1, CP_WAIT(1) leaves only G(p+2) pending, so B(p+1) (older
// group) is guaranteed complete. CP_WAIT(0) drains at the last pass.
// ---------------------------------------------------------------------------
__global__ __launch_bounds__(512, 1)
void out_mma(float* __restrict__ out) {
    extern __shared__ char sm[];
    u32 sb = smem_u32(sm);
    const int t = threadIdx.x, w = t >> 5, lane = t & 31;
    const int v0 = blockIdx.x * 128;
    const int g = lane >> 2, tg = lane & 3;
    const int m0 = (w >> 2) * 32, n0 = (w & 3) * 32;
    const char* wbase = reinterpret_cast<const char*>(g_wimg) + (size_t)16 * WIMG_BYTES;

    prefetch_G(sb + SM_G0, g_G, v0, t);             // group: G0
    prefetch_W(sb + SM_OB, wbase, t);               // group: B0

    float d[8][4];
#pragma unroll
    for (int i = 0; i < 8; ++i) { d[i][0] = d[i][1] = d[i][2] = d[i][3] = 0.f; }

    for (int p = 0; p < 8; ++p) {
        const u32 curG = (p & 1) ? SM_G1 : SM_G0;
        const u32 nxtG = (p & 1) ? SM_G0 : SM_G1;
        if (p + 1 < 8) {
            prefetch_G(sb + nxtG, g_G + (size_t)(p + 1) * V_N * 128, v0, t);
            CP_WAIT(1);   // G[p] + B[p] ready (only G[p+1] may remain)
        } else {
            CP_WAIT(0);
        }
        __syncthreads();

        mma_block_reg(reinterpret_cast<const float*>(sm + curG), sm + SM_OB,
                      w, lane, d);
        __syncthreads();   // B buffer free; staging buffer ownership flips

        if (p + 1 < 8)
            prefetch_W(sb + SM_OB, wbase + (size_t)(p + 1) * WIMG_BYTES, t);
    }

#pragma unroll
    for (int i = 0; i < 2; ++i) {
        int vA = v0 + m0 + i * 16 + g;
        int vB = vA + 8;
#pragma unroll
        for (int j = 0; j < 4; ++j) {
            int col = n0 + j * 8 + 2 * tg;
            if (vA < V_N)
                *reinterpret_cast<float2*>(out + (size_t)vA * 128 + col) =
                    make_float2(fmaxf(d[i * 4 + j][0], 0.f), fmaxf(d[i * 4 + j][1], 0.f));
            if (vB < V_N)
                *reinterpret_cast<float2*>(out + (size_t)vB * 128 + col) =
                    make_float2(fmaxf(d[i * 4 + j][2], 0.f), fmaxf(d[i * 4 + j][3], 0.f));
        }
    }
}

// ---------------------------------------------------------------------------
extern "C" void kernel_launch(void* const* d_in, const int* in_sizes, int n_in,
                              void* d_out, int out_size) {
    const float* emb = (const float*)d_in[0];
    const int*   a0  = (const int*)d_in[1];
    const int*   a1  = (const int*)d_in[2];
    const int*   a2  = (const int*)d_in[3];
    const int*   a3  = (const int*)d_in[4];
    const float* W1  = (const float*)d_in[5];
    const float* W2  = (const float*)d_in[6];
    float* out = (float*)d_out;

    cudaFuncSetAttribute(pre_mma, cudaFuncAttributeMaxDynamicSharedMemorySize, SM_PRE);
    cudaFuncSetAttribute(out_mma, cudaFuncAttributeMaxDynamicSharedMemorySize, SM_OUT);

    const int VT = (V_N + 127) / 128;   // 391 row-tiles

    w_prep_kernel<<<24 + ZERO_BLOCKS, 256>>>(W1, W2);
    pre_mma<<<VT, 512, SM_PRE>>>(emb);
    edge_kernel<<<dim3(E_N / 16, 8), 256>>>(a0, a1, a2, a3);
    out_mma<<<VT, 512, SM_OUT>>>(out);
}

// round 16
// speedup vs baseline: 1.5448x; 1.5448x over previous
#include <cuda_runtime.h>
#include <cuda_fp16.h>
#include <cstdint>
#include <cstddef>

#define V_N 50000
#define E_N 160000
#define SA  136      // bf16 row stride (272 B = 17 x 16B granules) — ldmatrix conflict-free

typedef unsigned long long ull;
typedef unsigned int u32;

// ---------------------------------------------------------------------------
// Device scratch
// g_tab: per (pass p, side s): [V][128] fp16, slab by = 2p+s.
// g_G:   per pass, segment-summed relu'd hidden (f32).
// g_wimg: 24 weight images (16 W1 + 8 W2), each [128 n][SA k] bf16 hi+lo.
// ---------------------------------------------------------------------------
__device__ __align__(128) __half g_tab[(size_t)16 * V_N * 128];
__device__ __align__(128) float  g_G[(size_t)8 * V_N * 128];
__device__ __align__(256) unsigned short g_wimg[(size_t)24 * 2 * 128 * SA];

#define WIMG_BLK   (2 * 128 * SA)
#define WIMG_BYTES (WIMG_BLK * 2)     // 69632 B

// smem layout for both GEMM kernels (A hi/lo pre-split + double-buffered B)
#define SM_A_HI  0
#define SM_A_LO  34816
#define SM_B0    69632
#define SM_B1    139264
#define SM_TOTAL 208896

// ---------------------------------------------------------------------------
static __device__ __forceinline__ u32 smem_u32(const void* p) {
    u32 a;
    asm("{ .reg .u64 t; cvta.to.shared.u64 t, %1; cvt.u32.u64 %0, t; }"
        : "=r"(a) : "l"(p));
    return a;
}
#define CP_ASYNC16(dst_u32, src_ptr) \
    asm volatile("cp.async.ca.shared.global [%0], [%1], 16;" \
                 :: "r"(dst_u32), "l"(src_ptr) : "memory")
#define CP_COMMIT()  asm volatile("cp.async.commit_group;" ::: "memory")
#define CP_WAIT(n)   asm volatile("cp.async.wait_group %0;" :: "n"(n) : "memory")

#define LDMX4(r0, r1, r2, r3, addr) \
    asm volatile("ldmatrix.sync.aligned.m8n8.x4.shared.b16 {%0,%1,%2,%3}, [%4];" \
                 : "=r"(r0), "=r"(r1), "=r"(r2), "=r"(r3) : "r"(addr))

static __device__ __forceinline__ void mma16816(float d[4], const u32 a[4], const u32 b[2]) {
    asm volatile(
        "mma.sync.aligned.m16n8k16.row.col.f32.bf16.bf16.f32 "
        "{%0,%1,%2,%3}, {%4,%5,%6,%7}, {%8,%9}, {%0,%1,%2,%3};"
        : "+f"(d[0]), "+f"(d[1]), "+f"(d[2]), "+f"(d[3])
        : "r"(a[0]), "r"(a[1]), "r"(a[2]), "r"(a[3]), "r"(b[0]), "r"(b[1]));
}

// Split a float2 into packed bf16x2 hi (truncated) and lo (residual, rn).
static __device__ __forceinline__ void split2(float2 v, u32& hi, u32& lo) {
    u32 ux = __float_as_uint(v.x), uy = __float_as_uint(v.y);
    hi = __byte_perm(ux, uy, 0x7632);
    float rx = v.x - __uint_as_float(ux & 0xFFFF0000u);
    float ry = v.y - __uint_as_float(uy & 0xFFFF0000u);
    asm("cvt.rn.bf16x2.f32 %0, %1, %2;" : "=r"(lo) : "f"(ry), "f"(rx));
}

// ---------------------------------------------------------------------------
// Split an f32 [128 rows][128 k] tile (row-major stride 128, rows clamped)
// into bf16 hi/lo smem tiles with stride SA. 256 threads: row t>>1,
// 64-float half (t&1).
// ---------------------------------------------------------------------------
static __device__ __forceinline__ void load_A_tile(const float* __restrict__ base,
                                                   int v0, char* sm, int t) {
    const int row  = t >> 1;
    const int half = (t & 1) * 64;
    int vg = v0 + row; if (vg >= V_N) vg = V_N - 1;
    const float4* src = reinterpret_cast<const float4*>(base + (size_t)vg * 128 + half);
    char* hi = sm + SM_A_HI + (size_t)(row * SA + half) * 2;
    char* lo = sm + SM_A_LO + (size_t)(row * SA + half) * 2;
#pragma unroll
    for (int q = 0; q < 16; ++q) {
        float4 x = src[q];
        u32 h01, l01, h23, l23;
        split2(make_float2(x.x, x.y), h01, l01);
        split2(make_float2(x.z, x.w), h23, l23);
        *reinterpret_cast<ull*>(hi + q * 8) = ((ull)h23 << 32) | h01;
        *reinterpret_cast<ull*>(lo + q * 8) = ((ull)l23 << 32) | l01;
    }
}

// ---------------------------------------------------------------------------
// 3-split 128x128x128 bf16 MMA, 8 warps, warp tile 64m x 32n.
// All fragments via ldmatrix.x4 (conflict-free at SA=136).
// Ah/Al/Bh/Bl are smem u32 base addresses. d[16][4].
// A x4 group (lane group mi): matrix mi = rows m0+(mi&1)*8.., cols k+(mi>>1)*8
//   -> regs (a0,a1,a2,a3) = {m,k},{m+8,k},{m,k+8},{m+8,k+8}  (mma A order)
// B x4 group: matrix mi = rows n0+(mi>>1)*8.., cols k+(mi&1)*8
//   -> regs = b[0][0],b[0][1],b[1][0],b[1][1]; second pair at +16 n-rows.
// ---------------------------------------------------------------------------
static __device__ __forceinline__ void mma_block(u32 Ah, u32 Al, u32 Bh, u32 Bl,
                                                 int w, int lane, float d[16][4]) {
    const int mi = lane >> 3;          // matrix index 0..3
    const int r  = lane & 7;           // row within 8x8 tile
    const int m0 = (w >> 2) * 64;
    const int n0 = (w & 3) * 32;

    const u32 aoff = (u32)(((m0 + ((mi & 1) << 3) + r) * SA + ((mi >> 1) << 3)) * 2);
    const u32 boff = (u32)(((n0 + ((mi >> 1) << 3) + r) * SA + ((mi & 1) << 3)) * 2);
    const u32 ROW16 = (u32)(16 * SA * 2);   // 16-row step (bytes)

#pragma unroll
    for (int ks = 0; ks < 8; ++ks) {
        const u32 kb2 = (u32)(ks * 32);     // 16 bf16 cols = 32 B
        u32 ah[4][4], al[4][4], bh[4][2], bl[4][2];
#pragma unroll
        for (int i = 0; i < 4; ++i) {
            LDMX4(ah[i][0], ah[i][1], ah[i][2], ah[i][3], Ah + aoff + i * ROW16 + kb2);
            LDMX4(al[i][0], al[i][1], al[i][2], al[i][3], Al + aoff + i * ROW16 + kb2);
        }
        LDMX4(bh[0][0], bh[0][1], bh[1][0], bh[1][1], Bh + boff + kb2);
        LDMX4(bh[2][0], bh[2][1], bh[3][0], bh[3][1], Bh + boff + ROW16 + kb2);
        LDMX4(bl[0][0], bl[0][1], bl[1][0], bl[1][1], Bl + boff + kb2);
        LDMX4(bl[2][0], bl[2][1], bl[3][0], bl[3][1], Bl + boff + ROW16 + kb2);
#pragma unroll
        for (int i = 0; i < 4; ++i)
#pragma unroll
            for (int j = 0; j < 4; ++j) {
                mma16816(d[i * 4 + j], ah[i], bh[j]);
                mma16816(d[i * 4 + j], ah[i], bl[j]);
                mma16816(d[i * 4 + j], al[i], bh[j]);
            }
    }
}

// Prefetch one weight image (69632 B = 17 x 16B per thread @256) + commit.
static __device__ __forceinline__ void prefetch_W(u32 dst_sb, const char* src, int t) {
#pragma unroll
    for (int i = 0; i < 17; ++i)
        CP_ASYNC16(dst_sb + (u32)(i * 4096 + t * 16), src + i * 4096 + t * 16);
    CP_COMMIT();
}

// ---------------------------------------------------------------------------
// Kernel: build weight images (blocks 0..23) + zero g_G (blocks 24..).
// blk 0..15 = W1 flat 128-row blocks (by=2p+s); 16..23 = W2[p].
// Image[n][k] = W[k][n] (transposed), split hi/lo.
// ---------------------------------------------------------------------------
#define ZERO_BLOCKS 2000
__global__ void w_prep_kernel(const float* __restrict__ W1, const float* __restrict__ W2) {
    const int blk = blockIdx.x;
    if (blk < 24) {
        const float* src = (blk < 16) ? (W1 + (size_t)blk * 16384)
                                      : (W2 + (size_t)(blk - 16) * 16384);
        unsigned short* hi = g_wimg + (size_t)blk * WIMG_BLK;
        unsigned short* lo = hi + 128 * SA;
        for (int idx = threadIdx.x; idx < 16384; idx += blockDim.x) {
            int n = idx >> 7, k = idx & 127;
            float x = src[(size_t)k * 128 + n];
            u32 u = __float_as_uint(x);
            float r = x - __uint_as_float(u & 0xFFFF0000u);
            u32 lob;
            asm("cvt.rn.bf16x2.f32 %0, %1, %2;" : "=r"(lob) : "f"(0.0f), "f"(r));
            hi[n * SA + k] = (unsigned short)(u >> 16);
            lo[n * SA + k] = (unsigned short)(lob & 0xFFFF);
        }
    } else {
        const int i = (blk - 24) * 256 + threadIdx.x;
        float4* g4 = reinterpret_cast<float4*>(g_G);
#pragma unroll
        for (int c = 0; c < 25; ++c)
            g4[(size_t)i + (size_t)c * (ZERO_BLOCKS * 256)] = make_float4(0.f, 0.f, 0.f, 0.f);
    }
}

// ---------------------------------------------------------------------------
// Kernel: tab[by] = emb @ W1blk[by] for all 16 by (fp16 out). 256 threads.
// ---------------------------------------------------------------------------
__global__ __launch_bounds__(256, 1)
void pre_mma(const float* __restrict__ emb) {
    extern __shared__ char sm[];
    u32 sb = smem_u32(sm);
    const int t = threadIdx.x, w = t >> 5, lane = t & 31;
    const int v0 = blockIdx.x * 128;
    const int g = lane >> 2, tg = lane & 3;
    const int m0 = (w >> 2) * 64, n0 = (w & 3) * 32;
    const char* wbase = reinterpret_cast<const char*>(g_wimg);

    prefetch_W(sb + SM_B0, wbase, t);
    load_A_tile(emb, v0, sm, t);

    for (int by = 0; by < 16; ++by) {
        const u32 cur = (by & 1) ? SM_B1 : SM_B0;
        const u32 nxt = (by & 1) ? SM_B0 : SM_B1;
        if (by + 1 < 16) {
            prefetch_W(sb + nxt, wbase + (size_t)(by + 1) * WIMG_BYTES, t);
            CP_WAIT(1);
        } else {
            CP_WAIT(0);
        }
        __syncthreads();

        float d[16][4];
#pragma unroll
        for (int i = 0; i < 16; ++i) { d[i][0] = d[i][1] = d[i][2] = d[i][3] = 0.f; }

        mma_block(sb + SM_A_HI, sb + SM_A_LO, sb + cur, sb + cur + 34816, w, lane, d);

        __half* base = g_tab + (size_t)by * V_N * 128;
#pragma unroll
        for (int i = 0; i < 4; ++i) {
            int vA = v0 + m0 + i * 16 + g;
            int vB = vA + 8;
#pragma unroll
            for (int j = 0; j < 4; ++j) {
                int col = n0 + j * 8 + 2 * tg;
                if (vA < V_N)
                    *reinterpret_cast<__half2*>(base + (size_t)vA * 128 + col) =
                        __floats2half2_rn(d[i * 4 + j][0], d[i * 4 + j][1]);
                if (vB < V_N)
                    *reinterpret_cast<__half2*>(base + (size_t)vB * 128 + col) =
                        __floats2half2_rn(d[i * 4 + j][2], d[i * 4 + j][3]);
            }
        }
        __syncthreads();   // all warps done with cur before it becomes prefetch dst
    }
}

// ---------------------------------------------------------------------------
// Kernel: edge phase — fp16 gather + add + relu + f32 vector-atomic scatter.
// ---------------------------------------------------------------------------
__global__ __launch_bounds__(256)
void edge_kernel(const int* __restrict__ a0p, const int* __restrict__ a1p,
                 const int* __restrict__ a2p, const int* __restrict__ a3p) {
    const int t    = threadIdx.x;
    const int p    = blockIdx.y;
    const int l    = p >> 1, ep = p & 1;
    const int* adj = (l == 0) ? a0p : (l == 1) ? a1p : (l == 2) ? a2p : a3p;

    const int e    = blockIdx.x * 16 + (t >> 4);
    const int half = t & 15;

    int2 sd = reinterpret_cast<const int2*>(adj)[e];
    int tgt = ep ? sd.y : sd.x;

    const __half* A = g_tab + (size_t)(2 * p) * V_N * 128;
    const __half* B = A + (size_t)V_N * 128;

    uint4 av = *reinterpret_cast<const uint4*>(A + (size_t)sd.x * 128 + half * 8);
    uint4 bv = *reinterpret_cast<const uint4*>(B + (size_t)sd.y * 128 + half * 8);

    float2 a0 = __half22float2(*reinterpret_cast<__half2*>(&av.x));
    float2 a1 = __half22float2(*reinterpret_cast<__half2*>(&av.y));
    float2 a2 = __half22float2(*reinterpret_cast<__half2*>(&av.z));
    float2 a3 = __half22float2(*reinterpret_cast<__half2*>(&av.w));
    float2 b0 = __half22float2(*reinterpret_cast<__half2*>(&bv.x));
    float2 b1 = __half22float2(*reinterpret_cast<__half2*>(&bv.y));
    float2 b2 = __half22float2(*reinterpret_cast<__half2*>(&bv.z));
    float2 b3 = __half22float2(*reinterpret_cast<__half2*>(&bv.w));

    float4 h0 = make_float4(fmaxf(a0.x + b0.x, 0.f), fmaxf(a0.y + b0.y, 0.f),
                            fmaxf(a1.x + b1.x, 0.f), fmaxf(a1.y + b1.y, 0.f));
    float4 h1 = make_float4(fmaxf(a2.x + b2.x, 0.f), fmaxf(a2.y + b2.y, 0.f),
                            fmaxf(a3.x + b3.x, 0.f), fmaxf(a3.y + b3.y, 0.f));

    float* gq = g_G + ((size_t)p * V_N + tgt) * 128 + half * 8;
    atomicAdd(reinterpret_cast<float4*>(gq), h0);
    atomicAdd(reinterpret_cast<float4*>(gq + 4), h1);
}

// ---------------------------------------------------------------------------
// Kernel: out = relu( sum_p G_p @ W2_p ), K=1024 in registers. 256 threads.
// Per pass: A tile split into smem, W image double-buffered via cp.async.
// ---------------------------------------------------------------------------
__global__ __launch_bounds__(256, 1)
void out_mma(float* __restrict__ out) {
    extern __shared__ char sm[];
    u32 sb = smem_u32(sm);
    const int t = threadIdx.x, w = t >> 5, lane = t & 31;
    const int v0 = blockIdx.x * 128;
    const int g = lane >> 2, tg = lane & 3;
    const int m0 = (w >> 2) * 64, n0 = (w & 3) * 32;
    const char* wbase = reinterpret_cast<const char*>(g_wimg) + (size_t)16 * WIMG_BYTES;

    prefetch_W(sb + SM_B0, wbase, t);

    float d[16][4];
#pragma unroll
    for (int i = 0; i < 16; ++i) { d[i][0] = d[i][1] = d[i][2] = d[i][3] = 0.f; }

    for (int p = 0; p < 8; ++p) {
        const u32 cur = (p & 1) ? SM_B1 : SM_B0;
        const u32 nxt = (p & 1) ? SM_B0 : SM_B1;
        load_A_tile(g_G + (size_t)p * V_N * 128, v0, sm, t);
        if (p + 1 < 8) {
            prefetch_W(sb + nxt, wbase + (size_t)(p + 1) * WIMG_BYTES, t);
            CP_WAIT(1);
        } else {
            CP_WAIT(0);
        }
        __syncthreads();

        mma_block(sb + SM_A_HI, sb + SM_A_LO, sb + cur, sb + cur + 34816, w, lane, d);
        __syncthreads();   // A smem + cur buffer reused next p
    }

#pragma unroll
    for (int i = 0; i < 4; ++i) {
        int vA = v0 + m0 + i * 16 + g;
        int vB = vA + 8;
#pragma unroll
        for (int j = 0; j < 4; ++j) {
            int col = n0 + j * 8 + 2 * tg;
            if (vA < V_N)
                *reinterpret_cast<float2*>(out + (size_t)vA * 128 + col) =
                    make_float2(fmaxf(d[i * 4 + j][0], 0.f), fmaxf(d[i * 4 + j][1], 0.f));
            if (vB < V_N)
                *reinterpret_cast<float2*>(out + (size_t)vB * 128 + col) =
                    make_float2(fmaxf(d[i * 4 + j][2], 0.f), fmaxf(d[i * 4 + j][3], 0.f));
        }
    }
}

// ---------------------------------------------------------------------------
extern "C" void kernel_launch(void* const* d_in, const int* in_sizes, int n_in,
                              void* d_out, int out_size) {
    const float* emb = (const float*)d_in[0];
    const int*   a0  = (const int*)d_in[1];
    const int*   a1  = (const int*)d_in[2];
    const int*   a2  = (const int*)d_in[3];
    const int*   a3  = (const int*)d_in[4];
    const float* W1  = (const float*)d_in[5];
    const float* W2  = (const float*)d_in[6];
    float* out = (float*)d_out;

    cudaFuncSetAttribute(pre_mma, cudaFuncAttributeMaxDynamicSharedMemorySize, SM_TOTAL);
    cudaFuncSetAttribute(out_mma, cudaFuncAttributeMaxDynamicSharedMemorySize, SM_TOTAL);

    const int VT = (V_N + 127) / 128;   // 391 row-tiles

    w_prep_kernel<<<24 + ZERO_BLOCKS, 256>>>(W1, W2);
    pre_mma<<<VT, 256, SM_TOTAL>>>(emb);
    edge_kernel<<<dim3(E_N / 16, 8), 256>>>(a0, a1, a2, a3);
    out_mma<<<VT, 256, SM_TOTAL>>>(out);
}

// round 17
// speedup vs baseline: 1.5653x; 1.0133x over previous
#include <cuda_runtime.h>
#include <cuda_fp16.h>
#include <cstdint>
#include <cstddef>

#define V_N 50000
#define E_N 160000
#define SA  136      // bf16 row stride (272 B = 17 x 16B granules) — ldmatrix conflict-free

typedef unsigned long long ull;
typedef unsigned int u32;

// ---------------------------------------------------------------------------
// Device scratch
// g_tab: per (pass p, side s): [V][128] fp16, slab by = 2p+s.
// g_G:   per pass, segment-summed relu'd hidden (f32).
// g_wimg: 24 weight images (16 W1 + 8 W2), each [128 n][SA k] bf16 hi+lo.
// ---------------------------------------------------------------------------
__device__ __align__(128) __half g_tab[(size_t)16 * V_N * 128];
__device__ __align__(128) float  g_G[(size_t)8 * V_N * 128];
__device__ __align__(256) unsigned short g_wimg[(size_t)24 * 2 * 128 * SA];

#define WIMG_BLK   (2 * 128 * SA)
#define WIMG_BYTES (WIMG_BLK * 2)     // 69632 B

// smem layout, both GEMM kernels (M=64 tile): A hi/lo + single B image
// A: 64 x SA bf16 = 17408 B each;  B: 128 x SA bf16 hi+lo = 69632 B
#define SM_A_HI  0
#define SM_A_LO  17408
#define SM_B     34816
#define SM_TOTAL 104448               // <= 113.5 KB -> 2 CTAs/SM

// ---------------------------------------------------------------------------
static __device__ __forceinline__ u32 smem_u32(const void* p) {
    u32 a;
    asm("{ .reg .u64 t; cvta.to.shared.u64 t, %1; cvt.u32.u64 %0, t; }"
        : "=r"(a) : "l"(p));
    return a;
}
#define CP_ASYNC16(dst_u32, src_ptr) \
    asm volatile("cp.async.ca.shared.global [%0], [%1], 16;" \
                 :: "r"(dst_u32), "l"(src_ptr) : "memory")
#define CP_COMMIT()  asm volatile("cp.async.commit_group;" ::: "memory")
#define CP_WAIT(n)   asm volatile("cp.async.wait_group %0;" :: "n"(n) : "memory")

#define LDMX4(r0, r1, r2, r3, addr) \
    asm volatile("ldmatrix.sync.aligned.m8n8.x4.shared.b16 {%0,%1,%2,%3}, [%4];" \
                 : "=r"(r0), "=r"(r1), "=r"(r2), "=r"(r3) : "r"(addr))

static __device__ __forceinline__ void mma16816(float d[4], const u32 a[4], const u32 b[2]) {
    asm volatile(
        "mma.sync.aligned.m16n8k16.row.col.f32.bf16.bf16.f32 "
        "{%0,%1,%2,%3}, {%4,%5,%6,%7}, {%8,%9}, {%0,%1,%2,%3};"
        : "+f"(d[0]), "+f"(d[1]), "+f"(d[2]), "+f"(d[3])
        : "r"(a[0]), "r"(a[1]), "r"(a[2]), "r"(a[3]), "r"(b[0]), "r"(b[1]));
}

// Split a float2 into packed bf16x2 hi (truncated) and lo (residual, rn).
static __device__ __forceinline__ void split2(float2 v, u32& hi, u32& lo) {
    u32 ux = __float_as_uint(v.x), uy = __float_as_uint(v.y);
    hi = __byte_perm(ux, uy, 0x7632);
    float rx = v.x - __uint_as_float(ux & 0xFFFF0000u);
    float ry = v.y - __uint_as_float(uy & 0xFFFF0000u);
    asm("cvt.rn.bf16x2.f32 %0, %1, %2;" : "=r"(lo) : "f"(ry), "f"(rx));
}

// ---------------------------------------------------------------------------
// Split an f32 [64 rows][128 k] tile (row-major stride 128, rows clamped)
// into bf16 hi/lo smem tiles with stride SA. 256 threads: row t>>2,
// 32-float quarter (t&3).
// ---------------------------------------------------------------------------
static __device__ __forceinline__ void load_A_tile(const float* __restrict__ base,
                                                   int v0, char* sm, int t) {
    const int row = t >> 2;
    const int q0  = (t & 3) * 32;
    int vg = v0 + row; if (vg >= V_N) vg = V_N - 1;
    const float4* src = reinterpret_cast<const float4*>(base + (size_t)vg * 128 + q0);
    char* hi = sm + SM_A_HI + (size_t)(row * SA + q0) * 2;
    char* lo = sm + SM_A_LO + (size_t)(row * SA + q0) * 2;
#pragma unroll
    for (int q = 0; q < 8; ++q) {
        float4 x = src[q];
        u32 h01, l01, h23, l23;
        split2(make_float2(x.x, x.y), h01, l01);
        split2(make_float2(x.z, x.w), h23, l23);
        *reinterpret_cast<ull*>(hi + q * 8) = ((ull)h23 << 32) | h01;
        *reinterpret_cast<ull*>(lo + q * 8) = ((ull)l23 << 32) | l01;
    }
}

// ---------------------------------------------------------------------------
// 3-split 64x128x128 bf16 MMA, 8 warps, warp tile 32m x 32n (2x4 warp grid).
// All fragments via ldmatrix.x4 (conflict-free at SA=136). d[8][4].
// A x4 (lane group mi): rows m0+(mi&1)*8.., cols k+(mi>>1)*8 -> mma A order.
// B x4: rows n0+(mi>>1)*8.., cols k+(mi&1)*8; second j-pair at +16 n-rows.
// ---------------------------------------------------------------------------
static __device__ __forceinline__ void mma_block(u32 Ah, u32 Al, u32 Bh, u32 Bl,
                                                 int w, int lane, float d[8][4]) {
    const int mi = lane >> 3;          // matrix index 0..3
    const int r  = lane & 7;           // row within 8x8 tile
    const int m0 = (w >> 2) * 32;      // warp m: 0 or 32
    const int n0 = (w & 3) * 32;       // warp n: 0,32,64,96

    const u32 aoff = (u32)(((m0 + ((mi & 1) << 3) + r) * SA + ((mi >> 1) << 3)) * 2);
    const u32 boff = (u32)(((n0 + ((mi >> 1) << 3) + r) * SA + ((mi & 1) << 3)) * 2);
    const u32 ROW16 = (u32)(16 * SA * 2);   // 16-row step (bytes)

#pragma unroll
    for (int ks = 0; ks < 8; ++ks) {
        const u32 kb2 = (u32)(ks * 32);     // 16 bf16 cols = 32 B
        u32 ah[2][4], al[2][4], bh[4][2], bl[4][2];
#pragma unroll
        for (int i = 0; i < 2; ++i) {
            LDMX4(ah[i][0], ah[i][1], ah[i][2], ah[i][3], Ah + aoff + i * ROW16 + kb2);
            LDMX4(al[i][0], al[i][1], al[i][2], al[i][3], Al + aoff + i * ROW16 + kb2);
        }
        LDMX4(bh[0][0], bh[0][1], bh[1][0], bh[1][1], Bh + boff + kb2);
        LDMX4(bh[2][0], bh[2][1], bh[3][0], bh[3][1], Bh + boff + ROW16 + kb2);
        LDMX4(bl[0][0], bl[0][1], bl[1][0], bl[1][1], Bl + boff + kb2);
        LDMX4(bl[2][0], bl[2][1], bl[3][0], bl[3][1], Bl + boff + ROW16 + kb2);
#pragma unroll
        for (int i = 0; i < 2; ++i)
#pragma unroll
            for (int j = 0; j < 4; ++j) {
                mma16816(d[i * 4 + j], ah[i], bh[j]);
                mma16816(d[i * 4 + j], ah[i], bl[j]);
                mma16816(d[i * 4 + j], al[i], bh[j]);
            }
    }
}

// Prefetch one weight image (69632 B = 17 x 16B per thread @256) + commit.
static __device__ __forceinline__ void prefetch_W(u32 dst_sb, const char* src, int t) {
#pragma unroll
    for (int i = 0; i < 17; ++i)
        CP_ASYNC16(dst_sb + (u32)(i * 4096 + t * 16), src + i * 4096 + t * 16);
    CP_COMMIT();
}

// ---------------------------------------------------------------------------
// Kernel: build weight images (blocks 0..23) + zero g_G (blocks 24..).
// blk 0..15 = W1 flat 128-row blocks (by=2p+s); 16..23 = W2[p].
// Image[n][k] = W[k][n] (transposed), split hi/lo.
// ---------------------------------------------------------------------------
#define ZERO_BLOCKS 2000
__global__ void w_prep_kernel(const float* __restrict__ W1, const float* __restrict__ W2) {
    const int blk = blockIdx.x;
    if (blk < 24) {
        const float* src = (blk < 16) ? (W1 + (size_t)blk * 16384)
                                      : (W2 + (size_t)(blk - 16) * 16384);
        unsigned short* hi = g_wimg + (size_t)blk * WIMG_BLK;
        unsigned short* lo = hi + 128 * SA;
        for (int idx = threadIdx.x; idx < 16384; idx += blockDim.x) {
            int n = idx >> 7, k = idx & 127;
            float x = src[(size_t)k * 128 + n];
            u32 u = __float_as_uint(x);
            float r = x - __uint_as_float(u & 0xFFFF0000u);
            u32 lob;
            asm("cvt.rn.bf16x2.f32 %0, %1, %2;" : "=r"(lob) : "f"(0.0f), "f"(r));
            hi[n * SA + k] = (unsigned short)(u >> 16);
            lo[n * SA + k] = (unsigned short)(lob & 0xFFFF);
        }
    } else {
        const int i = (blk - 24) * 256 + threadIdx.x;
        float4* g4 = reinterpret_cast<float4*>(g_G);
#pragma unroll
        for (int c = 0; c < 25; ++c)
            g4[(size_t)i + (size_t)c * (ZERO_BLOCKS * 256)] = make_float4(0.f, 0.f, 0.f, 0.f);
    }
}

// ---------------------------------------------------------------------------
// Kernel: tab[by] = emb @ W1blk[by] for all 16 by (fp16 out).
// 256 threads, M=64 tile, 2 CTAs/SM (cross-CTA load/mma overlap).
// ---------------------------------------------------------------------------
__global__ __launch_bounds__(256, 2)
void pre_mma(const float* __restrict__ emb) {
    extern __shared__ char sm[];
    u32 sb = smem_u32(sm);
    const int t = threadIdx.x, w = t >> 5, lane = t & 31;
    const int v0 = blockIdx.x * 64;
    const int g = lane >> 2, tg = lane & 3;
    const int m0 = (w >> 2) * 32, n0 = (w & 3) * 32;
    const char* wbase = reinterpret_cast<const char*>(g_wimg);

    load_A_tile(emb, v0, sm, t);

    for (int by = 0; by < 16; ++by) {
        prefetch_W(sb + SM_B, wbase + (size_t)by * WIMG_BYTES, t);
        CP_WAIT(0);
        __syncthreads();

        float d[8][4];
#pragma unroll
        for (int i = 0; i < 8; ++i) { d[i][0] = d[i][1] = d[i][2] = d[i][3] = 0.f; }

        mma_block(sb + SM_A_HI, sb + SM_A_LO, sb + SM_B, sb + SM_B + 34816, w, lane, d);

        __half* base = g_tab + (size_t)by * V_N * 128;
#pragma unroll
        for (int i = 0; i < 2; ++i) {
            int vA = v0 + m0 + i * 16 + g;
            int vB = vA + 8;
#pragma unroll
            for (int j = 0; j < 4; ++j) {
                int col = n0 + j * 8 + 2 * tg;
                if (vA < V_N)
                    *reinterpret_cast<__half2*>(base + (size_t)vA * 128 + col) =
                        __floats2half2_rn(d[i * 4 + j][0], d[i * 4 + j][1]);
                if (vB < V_N)
                    *reinterpret_cast<__half2*>(base + (size_t)vB * 128 + col) =
                        __floats2half2_rn(d[i * 4 + j][2], d[i * 4 + j][3]);
            }
        }
        __syncthreads();   // all warps done with B before next prefetch overwrites
    }
}

// ---------------------------------------------------------------------------
// Kernel: edge phase — fp16 gather + add + relu + f32 vector-atomic scatter.
// ---------------------------------------------------------------------------
__global__ __launch_bounds__(256)
void edge_kernel(const int* __restrict__ a0p, const int* __restrict__ a1p,
                 const int* __restrict__ a2p, const int* __restrict__ a3p) {
    const int t    = threadIdx.x;
    const int p    = blockIdx.y;
    const int l    = p >> 1, ep = p & 1;
    const int* adj = (l == 0) ? a0p : (l == 1) ? a1p : (l == 2) ? a2p : a3p;

    const int e    = blockIdx.x * 16 + (t >> 4);
    const int half = t & 15;

    int2 sd = reinterpret_cast<const int2*>(adj)[e];
    int tgt = ep ? sd.y : sd.x;

    const __half* A = g_tab + (size_t)(2 * p) * V_N * 128;
    const __half* B = A + (size_t)V_N * 128;

    uint4 av = *reinterpret_cast<const uint4*>(A + (size_t)sd.x * 128 + half * 8);
    uint4 bv = *reinterpret_cast<const uint4*>(B + (size_t)sd.y * 128 + half * 8);

    float2 a0 = __half22float2(*reinterpret_cast<__half2*>(&av.x));
    float2 a1 = __half22float2(*reinterpret_cast<__half2*>(&av.y));
    float2 a2 = __half22float2(*reinterpret_cast<__half2*>(&av.z));
    float2 a3 = __half22float2(*reinterpret_cast<__half2*>(&av.w));
    float2 b0 = __half22float2(*reinterpret_cast<__half2*>(&bv.x));
    float2 b1 = __half22float2(*reinterpret_cast<__half2*>(&bv.y));
    float2 b2 = __half22float2(*reinterpret_cast<__half2*>(&bv.z));
    float2 b3 = __half22float2(*reinterpret_cast<__half2*>(&bv.w));

    float4 h0 = make_float4(fmaxf(a0.x + b0.x, 0.f), fmaxf(a0.y + b0.y, 0.f),
                            fmaxf(a1.x + b1.x, 0.f), fmaxf(a1.y + b1.y, 0.f));
    float4 h1 = make_float4(fmaxf(a2.x + b2.x, 0.f), fmaxf(a2.y + b2.y, 0.f),
                            fmaxf(a3.x + b3.x, 0.f), fmaxf(a3.y + b3.y, 0.f));

    float* gq = g_G + ((size_t)p * V_N + tgt) * 128 + half * 8;
    atomicAdd(reinterpret_cast<float4*>(gq), h0);
    atomicAdd(reinterpret_cast<float4*>(gq + 4), h1);
}

// ---------------------------------------------------------------------------
// Kernel: out = relu( sum_p G_p @ W2_p ), K=1024 in registers.
// 256 threads, M=64 tile, 2 CTAs/SM.
// ---------------------------------------------------------------------------
__global__ __launch_bounds__(256, 2)
void out_mma(float* __restrict__ out) {
    extern __shared__ char sm[];
    u32 sb = smem_u32(sm);
    const int t = threadIdx.x, w = t >> 5, lane = t & 31;
    const int v0 = blockIdx.x * 64;
    const int g = lane >> 2, tg = lane & 3;
    const int m0 = (w >> 2) * 32, n0 = (w & 3) * 32;
    const char* wbase = reinterpret_cast<const char*>(g_wimg) + (size_t)16 * WIMG_BYTES;

    float d[8][4];
#pragma unroll
    for (int i = 0; i < 8; ++i) { d[i][0] = d[i][1] = d[i][2] = d[i][3] = 0.f; }

    for (int p = 0; p < 8; ++p) {
        prefetch_W(sb + SM_B, wbase + (size_t)p * WIMG_BYTES, t);
        load_A_tile(g_G + (size_t)p * V_N * 128, v0, sm, t);
        CP_WAIT(0);
        __syncthreads();

        mma_block(sb + SM_A_HI, sb + SM_A_LO, sb + SM_B, sb + SM_B + 34816, w, lane, d);
        __syncthreads();   // A + B smem reused next p
    }

#pragma unroll
    for (int i = 0; i < 2; ++i) {
        int vA = v0 + m0 + i * 16 + g;
        int vB = vA + 8;
#pragma unroll
        for (int j = 0; j < 4; ++j) {
            int col = n0 + j * 8 + 2 * tg;
            if (vA < V_N)
                *reinterpret_cast<float2*>(out + (size_t)vA * 128 + col) =
                    make_float2(fmaxf(d[i * 4 + j][0], 0.f), fmaxf(d[i * 4 + j][1], 0.f));
            if (vB < V_N)
                *reinterpret_cast<float2*>(out + (size_t)vB * 128 + col) =
                    make_float2(fmaxf(d[i * 4 + j][2], 0.f), fmaxf(d[i * 4 + j][3], 0.f));
        }
    }
}

// ---------------------------------------------------------------------------
extern "C" void kernel_launch(void* const* d_in, const int* in_sizes, int n_in,
                              void* d_out, int out_size) {
    const float* emb = (const float*)d_in[0];
    const int*   a0  = (const int*)d_in[1];
    const int*   a1  = (const int*)d_in[2];
    const int*   a2  = (const int*)d_in[3];
    const int*   a3  = (const int*)d_in[4];
    const float* W1  = (const float*)d_in[5];
    const float* W2  = (const float*)d_in[6];
    float* out = (float*)d_out;

    cudaFuncSetAttribute(pre_mma, cudaFuncAttributeMaxDynamicSharedMemorySize, SM_TOTAL);
    cudaFuncSetAttribute(out_mma, cudaFuncAttributeMaxDynamicSharedMemorySize, SM_TOTAL);

    const int VT = (V_N + 63) / 64;     // 782 row-tiles

    w_prep_kernel<<<24 + ZERO_BLOCKS, 256>>>(W1, W2);
    pre_mma<<<VT, 256, SM_TOTAL>>>(emb);
    edge_kernel<<<dim3(E_N / 16, 8), 256>>>(a0, a1, a2, a3);
    out_mma<<<VT, 256, SM_TOTAL>>>(out);
}